// round 15
// baseline (speedup 1.0000x reference)
#include <cuda_runtime.h>
#include <cuda_bf16.h>
#include <cstdint>
#include <cstddef>

typedef unsigned long long ull;

#define B_  64
#define S_  200
#define T_  199
#define H_  256
#define G4  1024
#define NI_ 50000

#define CL  8           // CTAs per cluster
#define NCL 16          // clusters (16*4 = 64 batches)
#define CPT 512         // compute threads
#define THR 640         // + 4 owner warps (2 per subgroup)
#define BARCNT 576      // 512 compute + 64 owners of one subgroup
#define TXB 2048u       // expect_tx: 8 CTAs x 32 elems x 8B per subgroup
#define K1_BLOCKS 1592  // 1592*8 warps = 199*64 (b,t) pairs exactly

// ------------------------- device scratch (no allocs allowed) ---------------
__device__ __align__(16) float g_xp[(size_t)T_ * B_ * G4];      // xp + bias, [t][b][1024]
__device__ __align__(16) float g_states[(size_t)T_ * B_ * H_];  // masked h outputs [t][b][256]
__device__ unsigned char g_mask[T_ * B_];
__device__ unsigned g_k3done;
__device__ float2 g_part[K1_BLOCKS];

// ------------------------- helpers ------------------------------------------
__device__ __forceinline__ ull pk2(float lo, float hi) {
    ull r; asm("mov.b64 %0, {%1, %2};" : "=l"(r) : "f"(lo), "f"(hi)); return r;
}
__device__ __forceinline__ void upk2(ull v, float& lo, float& hi) {
    asm("mov.b64 {%0, %1}, %2;" : "=f"(lo), "=f"(hi) : "l"(v));
}
__device__ __forceinline__ void fma2(ull& acc, ull a, ull b) {
    asm("fma.rn.f32x2 %0, %1, %2, %0;" : "+l"(acc) : "l"(a), "l"(b));
}
__device__ __forceinline__ ull add2(ull a, ull b) {
    ull r; asm("add.rn.f32x2 %0, %1, %2;" : "=l"(r) : "l"(a), "l"(b)); return r;
}
__device__ __forceinline__ float tanha(float x) {
    float y; asm("tanh.approx.f32 %0, %1;" : "=f"(y) : "f"(x)); return y;
}
__device__ __forceinline__ float siga(float x) {
    return fmaf(tanha(0.5f * x), 0.5f, 0.5f);
}
__device__ __forceinline__ unsigned smem_u32(const void* p) {
    unsigned a;
    asm("{ .reg .u64 t; cvta.to.shared.u64 t, %1; cvt.u32.u64 %0, t; }" : "=r"(a) : "l"(p));
    return a;
}
__device__ __forceinline__ unsigned ctarank_() {
    unsigned r; asm("mov.u32 %0, %%cluster_ctarank;" : "=r"(r)); return r;
}
__device__ __forceinline__ unsigned mapa_(unsigned addr, unsigned rank) {
    unsigned r; asm("mapa.shared::cluster.u32 %0, %1, %2;" : "=r"(r) : "r"(addr), "r"(rank));
    return r;
}
__device__ __forceinline__ void mbar_init(unsigned addr, unsigned cnt) {
    asm volatile("mbarrier.init.shared.b64 [%0], %1;" :: "r"(addr), "r"(cnt) : "memory");
}
__device__ __forceinline__ void mbar_expect_tx(unsigned addr, unsigned bytes) {
    asm volatile("mbarrier.arrive.expect_tx.shared.b64 _, [%0], %1;"
                 :: "r"(addr), "r"(bytes) : "memory");
}
// remote store whose completion posts tx bytes on the destination CTA's barrier
__device__ __forceinline__ void st_async64(unsigned raddr, ull v, unsigned rmbar) {
    asm volatile("st.async.shared::cluster.mbarrier::complete_tx::bytes.b64 [%0], %1, [%2];"
                 :: "r"(raddr), "l"(v), "r"(rmbar) : "memory");
}
__device__ __forceinline__ void mbar_wait(unsigned addr, int parity) {
    asm volatile(
        "{\n\t.reg .pred P;\n\t"
        "WL_%=:\n\t"
        "mbarrier.try_wait.parity.acquire.cta.shared::cta.b64 P, [%0], %1, 0x989680;\n\t"
        "@P bra.uni WD_%=;\n\t"
        "bra.uni WL_%=;\n\t"
        "WD_%=:\n\t}"
        :: "r"(addr), "r"(parity) : "memory");
}
__device__ __forceinline__ void cluster_sync_() {
    asm volatile("barrier.cluster.arrive.aligned;" ::: "memory");
    asm volatile("barrier.cluster.wait.aligned;" ::: "memory");
}

// ============================================================================
// K1: x_proj (+bias) -> g_xp, mask bytes, reset k3 flag. One warp per (b,t).
// ============================================================================
__global__ void k1_prep(const int* __restrict__ items, const int* __restrict__ actions,
                        const float* __restrict__ WihT, const float* __restrict__ b_lstm) {
    if (blockIdx.x == 0 && threadIdx.x == 0) g_k3done = 0u;
    int gw = blockIdx.x * 8 + (threadIdx.x >> 5);
    int lane = threadIdx.x & 31;
    if (gw >= T_ * B_) return;
    int b = gw & 63, t = gw >> 6;
    int it = items[b * S_ + t];
    int ac = actions[b * S_ + t];
    bool m = (it != 0);
    const float4* ra = (const float4*)(WihT + (size_t)it * G4);
    const float4* rb = (const float4*)(WihT + (size_t)(NI_ + ac) * G4);
    const float4* bi = (const float4*)b_lstm;
    float4* dst = (float4*)(g_xp + ((size_t)t * B_ + b) * G4);
#pragma unroll
    for (int p = 0; p < 8; p++) {
        int idx = lane + 32 * p;
        float4 bv = bi[idx];
        float4 o;
        if (m) {
            float4 a = ra[idx], c = rb[idx];
            o = make_float4(a.x + c.x + bv.x, a.y + c.y + bv.y,
                            a.z + c.z + bv.z, a.w + c.w + bv.w);
        } else {
            o = bv;
        }
        dst[idx] = o;
    }
    if (lane == 0) g_mask[t * B_ + b] = m ? 1 : 0;
}

// profiling-alignment no-ops (2 launches so ncu -s 5 -c 1 lands on k2_lstm)
__global__ void knop() {}

// ============================================================================
// K2: pipelined LSTM (R11 backbone). 16 clusters x 8 CTAs; cluster owns 4
// batches split into subgroups A={b0,b0+1}, B={b0+2,b0+3}. CTA rank r owns
// 128 gate rows (32 h-elems x 4 gates), K=256.
// CHANGE vs R11: 2 owner warps per subgroup; lanes pair per h-elem —
// role0 reduces K-slices 0-3 / role1 slices 4-7, combine via shfl.bfly,
// role r runs activations for batch r only, each role st.asyncs 4 peers
// (rank-rotated). Owner critical chain ~halves; protocol identical.
// ============================================================================
__global__ void __launch_bounds__(THR, 1) __cluster_dims__(CL, 1, 1)
k2_lstm(const float* __restrict__ Whh) {
    __shared__ __align__(16) ull smh[2][2][256];   // [sg][buf][j] = {h_b0,h_b1}
    __shared__ __align__(16) ull smp[2][8][128];   // [sg][ks][col]
    __shared__ __align__(8)  ull mbar[4];          // [sg*2+buf]

    const int tid = threadIdx.x;
    const unsigned rank = ctarank_();
    const int b0 = (blockIdx.x >> 3) * 4;

    // zero h buffers (8 KB); init + pre-arm all 4 barriers
    for (int i = tid; i < 512; i += THR)
        ((float4*)smh)[i] = make_float4(0.f, 0.f, 0.f, 0.f);
    if (tid < 4) mbar_init(smem_u32(&mbar[tid]), 1);
    __syncthreads();
    if (tid == 0) {
#pragma unroll
        for (int i = 0; i < 4; i++) mbar_expect_tx(smem_u32(&mbar[i]), TXB);
    }
    __syncthreads();
    cluster_sync_();   // arming + zeroed tiles visible before any peer store

    const unsigned mbA0 = smem_u32(&mbar[0]), mbA1 = smem_u32(&mbar[1]);
    const unsigned mbB0 = smem_u32(&mbar[2]), mbB1 = smem_u32(&mbar[3]);

    if (tid < CPT) {
        // ---------------- compute role (identical to R11 winner) ------------
        const int ks = tid >> 6;    // K-slice: j in [32ks, 32ks+32)
        const int u  = tid & 63;    // cols u and u+64

        ull   W1p[32];
        float W2[32];
        {
            const int r1 = (u >> 5) * 256 + 32 * (int)rank + (u & 31);
            const int r2 = (2 + (u >> 5)) * 256 + 32 * (int)rank + (u & 31);
            const float4* p1 = (const float4*)(Whh + (size_t)r1 * H_ + ks * 32);
            const float4* p2 = (const float4*)(Whh + (size_t)r2 * H_ + ks * 32);
#pragma unroll
            for (int q4 = 0; q4 < 8; q4++) {
                float4 v = p1[q4];
                W1p[q4 * 4 + 0] = pk2(v.x, v.x); W1p[q4 * 4 + 1] = pk2(v.y, v.y);
                W1p[q4 * 4 + 2] = pk2(v.z, v.z); W1p[q4 * 4 + 3] = pk2(v.w, v.w);
                float4 w = p2[q4];
                W2[q4 * 4 + 0] = w.x; W2[q4 * 4 + 1] = w.y;
                W2[q4 * 4 + 2] = w.z; W2[q4 * 4 + 3] = w.w;
            }
        }

        for (int t = 0; t < T_; t++) {
            const int buf = t & 1;
            const int par = ((t >> 1) + (t & 1) + 1) & 1;

            // ---- subgroup A ----
            if (t > 0) mbar_wait(buf ? mbA1 : mbA0, par);
            {
                ull a1 = 0, a2 = 0;
                const ulonglong2* hb = (const ulonglong2*)&smh[0][buf][ks * 32];
#pragma unroll
                for (int j2 = 0; j2 < 16; j2++) {
                    ulonglong2 hx = hb[j2];
                    fma2(a1, W1p[2 * j2], hx.x);
                    fma2(a2, pk2(W2[2 * j2], W2[2 * j2]), hx.x);
                    fma2(a1, W1p[2 * j2 + 1], hx.y);
                    fma2(a2, pk2(W2[2 * j2 + 1], W2[2 * j2 + 1]), hx.y);
                }
                smp[0][ks][u]      = a1;
                smp[0][ks][u + 64] = a2;
            }
            asm volatile("bar.arrive 2, %0;" :: "n"(BARCNT) : "memory");

            // ---- subgroup B ----
            if (t > 0) mbar_wait(buf ? mbB1 : mbB0, par);
            {
                ull a1 = 0, a2 = 0;
                const ulonglong2* hb = (const ulonglong2*)&smh[1][buf][ks * 32];
#pragma unroll
                for (int j2 = 0; j2 < 16; j2++) {
                    ulonglong2 hx = hb[j2];
                    fma2(a1, W1p[2 * j2], hx.x);
                    fma2(a2, pk2(W2[2 * j2], W2[2 * j2]), hx.x);
                    fma2(a1, W1p[2 * j2 + 1], hx.y);
                    fma2(a2, pk2(W2[2 * j2 + 1], W2[2 * j2 + 1]), hx.y);
                }
                smp[1][ks][u]      = a1;
                smp[1][ks][u + 64] = a2;
            }
            asm volatile("bar.arrive 3, %0;" :: "n"(BARCNT) : "memory");
        }
    } else {
        // ------- owner role: 2 warps per subgroup, lane-pair per h-elem -----
        const int ow = tid - CPT;          // 0..127
        const int sg = ow >> 6;            // subgroup
        const int q  = ow & 63;            // index within subgroup
        const int e  = q >> 1;             // h-elem within CTA (0..31)
        const int role = q & 1;            // batch within pair / K-half
        const int bMine = b0 + 2 * sg + role;
        const int jg = 32 * (int)rank + e; // global h index owned
        const int kb = role * 4;           // my K-slices: kb..kb+3
        const unsigned mb0 = sg ? mbB0 : mbA0;
        const unsigned mb1 = sg ? mbB1 : mbA1;

        float cst = 0.f, hst = 0.f;
        unsigned char mk = g_mask[bMine];
        const float* xb = g_xp + (size_t)bMine * G4 + jg;   // + gate*256
        float xpi = xb[0], xpf = xb[256], xpg = xb[512], xpo = xb[768];

        for (int t = 0; t < T_; t++) {
            const int buf = t & 1;
            const int par = ((t >> 1) + (t & 1) + 1) & 1;
            const unsigned mba = buf ? mb1 : mb0;
            if (t > 0) {
                mbar_wait(mba, par);                   // observe flip
                if (q == 0) mbar_expect_tx(mba, TXB);  // re-arm for t+2: one lane/sg
            }
            if (sg == 0)
                asm volatile("bar.sync 2, %0;" :: "n"(BARCNT) : "memory");
            else
                asm volatile("bar.sync 3, %0;" :: "n"(BARCNT) : "memory");

            // half reduce: my 4 K-slices x 4 gates (16 LDS.64 + 12 add2)
            ull s0 = smp[sg][kb][e],      s1 = smp[sg][kb][32 + e],
                s2 = smp[sg][kb][64 + e], s3 = smp[sg][kb][96 + e];
#pragma unroll
            for (int k = 1; k < 4; k++) {
                s0 = add2(s0, smp[sg][kb + k][e]);
                s1 = add2(s1, smp[sg][kb + k][32 + e]);
                s2 = add2(s2, smp[sg][kb + k][64 + e]);
                s3 = add2(s3, smp[sg][kb + k][96 + e]);
            }
            // combine role halves (partner has the other 4 slices)
            s0 = add2(s0, __shfl_xor_sync(0xffffffffu, s0, 1));
            s1 = add2(s1, __shfl_xor_sync(0xffffffffu, s1, 1));
            s2 = add2(s2, __shfl_xor_sync(0xffffffffu, s2, 1));
            s3 = add2(s3, __shfl_xor_sync(0xffffffffu, s3, 1));

            // extract my batch's gate scalars, add xp
            float ia, ib, fa, fb, ga, gb, oa, ob;
            upk2(s0, ia, ib); upk2(s1, fa, fb); upk2(s2, ga, gb); upk2(s3, oa, ob);
            float iv = (role ? ib : ia) + xpi;
            float fv = (role ? fb : fa) + xpf;
            float gv = (role ? gb : ga) + xpg;
            float ov = (role ? ob : oa) + xpo;

            float ii = siga(iv), ff = siga(fv), gt = tanha(gv), oo = siga(ov);
            float cn = ff * cst + ii * gt;
            float hn = oo * tanha(cn);
            float out;
            if (mk) { cst = cn; hst = hn; out = hn; } else out = 0.f;

            // pack {h_b0, h_b1} (partner holds the other batch)
            float hpart = __shfl_xor_sync(0xffffffffu, hst, 1);
            ull hull = role ? pk2(hpart, hst) : pk2(hst, hpart);

            // broadcast h(t+1): role0 -> peers rank+1..+4, role1 -> rank+5..+8
            if (t + 1 < T_) {
                unsigned loc = smem_u32(&smh[sg][1 - buf][jg]);
                unsigned mbn = buf ? mb0 : mb1;
#pragma unroll
                for (int p = 0; p < 4; p++) {
                    unsigned rr = (rank + 1u + (unsigned)(role * 4 + p)) & 7u;
                    st_async64(mapa_(loc, rr), hull, mapa_(mbn, rr));
                }
            }

            // off critical path: states store + next-step prefetch
            g_states[((size_t)t * B_ + bMine) * H_ + jg] = out;
            if (t + 1 < T_) {
                const float* xp = xb + (size_t)(t + 1) * B_ * G4;
                xpi = xp[0]; xpf = xp[256]; xpg = xp[512]; xpo = xp[768];
                mk = g_mask[(t + 1) * B_ + bMine];
            }
        }
    }
    cluster_sync_();  // no CTA exits while peers' remote ops may be in flight
}

// ============================================================================
// K3: query logits + per-(b,t) NLL; block partials + fused deterministic
// last-block final reduction. One warp per (b,t).
// ============================================================================
__global__ void k3_loss(const int* __restrict__ items, const int* __restrict__ actions,
                        const float* __restrict__ temb, const float* __restrict__ Wq,
                        const float* __restrict__ bq, float* __restrict__ out) {
    __shared__ float2 sred[8];
    __shared__ unsigned slast;
    int gw = blockIdx.x * 8 + (threadIdx.x >> 5);
    int lane = threadIdx.x & 31;
    float nll = 0.f, cnt = 0.f;
    int b = gw & 63, t = gw >> 6;
    int qit = items[b * S_ + t + 1];
    if (qit != 0) {
        const float4* sv = (const float4*)(g_states + ((size_t)t * B_ + b) * H_);
        const float4* ev = (const float4*)(temb + (size_t)qit * H_);
        const float4* w0 = (const float4*)Wq;
        const float4* w1 = (const float4*)(Wq + H_);
        float d0 = 0.f, d1 = 0.f;
#pragma unroll
        for (int p = 0; p < 2; p++) {
            int idx = lane * 2 + p;
            float4 s = sv[idx], e = ev[idx], a = w0[idx], c = w1[idx];
            float es;
            es = e.x * s.x; d0 += es * a.x; d1 += es * c.x;
            es = e.y * s.y; d0 += es * a.y; d1 += es * c.y;
            es = e.z * s.z; d0 += es * a.z; d1 += es * c.z;
            es = e.w * s.w; d0 += es * a.w; d1 += es * c.w;
        }
        ull d = pk2(d0, d1);
#pragma unroll
        for (int off = 16; off; off >>= 1)
            d = add2(d, __shfl_xor_sync(0xffffffffu, d, off));
        upk2(d, d0, d1);
        if (lane == 0) {
            float q0 = d0 + bq[0], q1 = d1 + bq[1];
            int tgt = actions[b * S_ + t + 1];
            float mx = fmaxf(q0, q1), mn = fminf(q0, q1);
            float lse = mx + log1pf(__expf(mn - mx));
            nll = lse - (tgt ? q1 : q0);
            cnt = 1.f;
        }
    }
    if (lane == 0) sred[threadIdx.x >> 5] = make_float2(nll, cnt);
    __syncthreads();
    if (threadIdx.x == 0) {
        float s = 0.f, c = 0.f;
#pragma unroll
        for (int i = 0; i < 8; i++) { s += sred[i].x; c += sred[i].y; }
        g_part[blockIdx.x] = make_float2(s, c);
        __threadfence();
        unsigned o = atomicAdd(&g_k3done, 1u);
        slast = (o == K1_BLOCKS - 1) ? 1u : 0u;
    }
    __syncthreads();
    if (slast) {
        __shared__ float ss[256], sc[256];
        __threadfence();
        float s = 0.f, c = 0.f;
        for (int i = threadIdx.x; i < K1_BLOCKS; i += 256) {
            float2 v = g_part[i];
            s += v.x; c += v.y;
        }
        ss[threadIdx.x] = s; sc[threadIdx.x] = c;
        __syncthreads();
        for (int st = 128; st; st >>= 1) {
            if (threadIdx.x < st) {
                ss[threadIdx.x] += ss[threadIdx.x + st];
                sc[threadIdx.x] += sc[threadIdx.x + st];
            }
            __syncthreads();
        }
        if (threadIdx.x == 0) out[0] = ss[0] / sc[0];
    }
}

// ============================================================================
extern "C" void kernel_launch(void* const* d_in, const int* in_sizes, int n_in,
                              void* d_out, int out_size) {
    const int*   items   = (const int*)d_in[0];
    const int*   actions = (const int*)d_in[1];
    const float* WihT    = (const float*)d_in[2];
    const float* Whh     = (const float*)d_in[3];
    const float* b_lstm  = (const float*)d_in[4];
    const float* temb    = (const float*)d_in[5];
    const float* Wq      = (const float*)d_in[6];
    const float* bq      = (const float*)d_in[7];
    (void)in_sizes; (void)n_in; (void)out_size;

    k1_prep<<<K1_BLOCKS, 256>>>(items, actions, WihT, b_lstm);
    knop<<<1, 1>>>();   // alignment: put k2_lstm at ncu's profiled slot (-s 5)
    knop<<<1, 1>>>();
    k2_lstm<<<NCL * CL, THR>>>(Whh);
    k3_loss<<<K1_BLOCKS, 256>>>(items, actions, temb, Wq, bq, (float*)d_out);
}